// round 1
// baseline (speedup 1.0000x reference)
#include <cuda_runtime.h>
#include <math.h>
#include <stdint.h>

#define NN 100000
#define DD 128
#define CC 16
#define SS 16
#define EE 3200000
#define KK 64
#define NIT 4

// ---------------- persistent device state (reset every launch) ----------------
__device__ unsigned int        g_nbr[NN];      // per-node 16-bit class neighbor mask (accumulative)
__device__ unsigned int        g_delta[NN];    // classes that newly added this node last selection
__device__ unsigned char      g_known[NN];
__device__ float               g_hx[CC * DD];
__device__ float               g_hxn[CC * DD]; // normalized hx
__device__ int                 g_last[CC * KK];
__device__ int                 g_candCnt[CC];
__device__ unsigned long long  g_candKeys[(size_t)CC * NN]; // 12.8 MB scratch

// ---------------- helpers ----------------
__device__ __forceinline__ unsigned ford(float f) {
    unsigned u = __float_as_uint(f);
    return (u >> 31) ? ~u : (u | 0x80000000u);
}
__device__ __forceinline__ float iford(unsigned u) {
    unsigned v = (u >> 31) ? (u & 0x7FFFFFFFu) : ~u;
    return __uint_as_float(v);
}

// ---------------- init ----------------
__global__ void k_init0() {
    int stride = gridDim.x * blockDim.x;
    for (int v = blockIdx.x * blockDim.x + threadIdx.x; v < NN; v += stride) {
        g_nbr[v] = 0u;
        g_delta[v] = 0u;
        g_known[v] = 0;
    }
}
__global__ void k_init1(const int* __restrict__ seeds) {
    int tid = threadIdx.x; // 256 = C*S
    if (tid < CC * SS) {
        int c = tid >> 4;
        int v = seeds[tid];
        g_known[v] = 1;
        atomicOr(&g_delta[v], 1u << c);
    }
}

// ---------------- memory step: hx = tanh((attend(es[last], q) [+hx]) @ W) ----------------
__global__ void k_memory(const float* __restrict__ es, const float* __restrict__ W,
                         const int* __restrict__ seeds, int kk, int t,
                         float* __restrict__ outHxes) {
    const int c = blockIdx.x;
    const int d = threadIdx.x; // 128 threads
    __shared__ float s_inp[KK * DD];
    __shared__ float s_q[DD];
    __shared__ float s_a[KK];
    __shared__ float s_pre[DD];
    __shared__ float s_red[4];

    const int* lp = (t == 0) ? (seeds + c * kk) : (g_last + c * KK);

    for (int j = 0; j < kk; j++) {
        int node = lp[j];
        s_inp[j * DD + d] = es[(size_t)node * DD + d];
    }
    float hprev = (t > 0) ? g_hx[c * DD + d] : 0.0f;
    if (t == 0) {
        float s = 0.0f;
        for (int j = 0; j < kk; j++) s += s_inp[j * DD + d];
        s_q[d] = s / (float)kk;
    } else {
        s_q[d] = hprev;
    }
    __syncthreads();

    // logits[j] = dot(inp_j, q) / sqrt(D)
    int lane = d & 31, wid = d >> 5;
    for (int j = wid; j < kk; j += 4) {
        float p = 0.0f;
#pragma unroll
        for (int q = 0; q < 4; q++) {
            int dd = lane + 32 * q;
            p += s_inp[j * DD + dd] * s_q[dd];
        }
#pragma unroll
        for (int o = 16; o; o >>= 1) p += __shfl_xor_sync(0xffffffffu, p, o);
        if (lane == 0) s_a[j] = p / sqrtf(128.0f);
    }
    __syncthreads();
    if (d == 0) {
        float m = s_a[0];
        for (int j = 1; j < kk; j++) m = fmaxf(m, s_a[j]);
        float sum = 0.0f;
        for (int j = 0; j < kk; j++) { float e = expf(s_a[j] - m); s_a[j] = e; sum += e; }
        for (int j = 0; j < kk; j++) s_a[j] /= sum;
    }
    __syncthreads();
    float ctx = 0.0f;
    for (int j = 0; j < kk; j++) ctx += s_a[j] * s_inp[j * DD + d];
    s_pre[d] = ctx + hprev;
    __syncthreads();

    float acc = 0.0f;
    for (int i = 0; i < DD; i++) acc += s_pre[i] * W[i * DD + d];
    float h = tanhf(acc);
    g_hx[c * DD + d] = h;
    outHxes[(t * CC + c) * DD + d] = h;

    float ss = h * h;
#pragma unroll
    for (int o = 16; o; o >>= 1) ss += __shfl_xor_sync(0xffffffffu, ss, o);
    if (lane == 0) s_red[wid] = ss;
    __syncthreads();
    float ns = s_red[0] + s_red[1] + s_red[2] + s_red[3];
    g_hxn[c * DD + d] = h / (sqrtf(ns) + 1e-8f);
    if (d == 0) g_candCnt[c] = 0;
}

// ---------------- incremental neighbor-mask update over edges ----------------
__global__ void k_edges(const int* __restrict__ src, const int* __restrict__ dst, int e) {
    int stride = gridDim.x * blockDim.x;
    int gt = blockIdx.x * blockDim.x + threadIdx.x;
    int e4 = e >> 2;
    const int4* s4 = reinterpret_cast<const int4*>(src);
    for (int i = gt; i < e4; i += stride) {
        int4 s = s4[i];
        unsigned m;
        m = g_delta[s.x]; if (m) atomicOr(&g_nbr[dst[4 * i + 0]], m);
        m = g_delta[s.y]; if (m) atomicOr(&g_nbr[dst[4 * i + 1]], m);
        m = g_delta[s.z]; if (m) atomicOr(&g_nbr[dst[4 * i + 2]], m);
        m = g_delta[s.w]; if (m) atomicOr(&g_nbr[dst[4 * i + 3]], m);
    }
    int tail = e & 3, base = e - tail;
    if (gt < tail) {
        int s = src[base + gt];
        unsigned m = g_delta[s];
        if (m) atomicOr(&g_nbr[dst[base + gt]], m);
    }
}

// ---------------- promote last selections to known, clear delta ----------------
__global__ void k_promote() {
    int stride = gridDim.x * blockDim.x;
    for (int v = blockIdx.x * blockDim.x + threadIdx.x; v < NN; v += stride) {
        unsigned m = g_delta[v];
        if (m) { g_known[v] = 1; g_delta[v] = 0u; }
    }
}

// ---------------- candidate compaction + cosine scoring (warp per node) ----------------
__global__ void k_compact(const float* __restrict__ es) {
    __shared__ float sh[CC * DD];
    for (int i = threadIdx.x; i < CC * DD; i += blockDim.x) sh[i] = g_hxn[i];
    __syncthreads();
    const int lane = threadIdx.x & 31;
    const int gw = (blockIdx.x * blockDim.x + threadIdx.x) >> 5;
    const int nw = (gridDim.x * blockDim.x) >> 5;
    for (int v = gw; v < NN; v += nw) {
        unsigned m = g_nbr[v];
        if (m == 0u) continue;
        if (g_known[v]) continue;
        const float4 r = reinterpret_cast<const float4*>(es)[(size_t)v * 32 + lane];
        float ss = r.x * r.x + r.y * r.y + r.z * r.z + r.w * r.w;
#pragma unroll
        for (int o = 16; o; o >>= 1) ss += __shfl_xor_sync(0xffffffffu, ss, o);
        float inv = 1.0f / (sqrtf(ss) + 1e-8f);
        while (m) {
            int c = __ffs(m) - 1;
            m &= m - 1;
            const float4 h = reinterpret_cast<const float4*>(sh + c * DD)[lane];
            float dp = r.x * h.x + r.y * h.y + r.z * h.z + r.w * h.w;
#pragma unroll
            for (int o = 16; o; o >>= 1) dp += __shfl_xor_sync(0xffffffffu, dp, o);
            if (lane == 0) {
                float score = dp * inv;
                unsigned long long key =
                    ((unsigned long long)ford(score) << 32) |
                    (unsigned long long)(0xFFFFFFFFu - (unsigned)v);
                int p = atomicAdd(&g_candCnt[c], 1);
                g_candKeys[(size_t)c * NN + p] = key;
            }
        }
    }
}

// ---------------- exact top-K per class: radix-select threshold + bitonic sort ----------------
__global__ void k_topk(float* __restrict__ outP, float* __restrict__ outE, int t) {
    const int c = blockIdx.x;
    const int tid = threadIdx.x;
    const int BD = 256;
    __shared__ unsigned int hist[4096];
    __shared__ unsigned long long sbuf[512];
    __shared__ int s_b, s_cum, s_stop, s_scnt;

    const unsigned long long* keys = g_candKeys + (size_t)c * NN;
    int cnt = g_candCnt[c];
    int r = cnt < KK ? cnt : KK;

    unsigned long long prefix = 0ULL;
    int sf = 64;
    if (cnt > 256) {
        int rr = r;
        for (int shift = 52; shift >= 4; shift -= 12) {
            for (int i = tid; i < 4096; i += BD) hist[i] = 0u;
            __syncthreads();
            for (int i = tid; i < cnt; i += BD) {
                unsigned long long key = keys[i];
                if (sf >= 64 || (key >> sf) == prefix)
                    atomicAdd(&hist[(unsigned)((key >> shift) & 0xFFFULL)], 1u);
            }
            __syncthreads();
            if (tid == 0) {
                int cum = 0, b = 4095;
                for (; b > 0; --b) {
                    int h = (int)hist[b];
                    if (cum + h >= rr) break;
                    cum += h;
                }
                s_b = b;
                s_cum = cum;
                int aboveTot = (r - rr) + cum;
                s_stop = (aboveTot + (int)hist[b] <= 256) ? 1 : 0;
            }
            __syncthreads();
            prefix = (prefix << 12) | (unsigned long long)s_b;
            rr -= s_cum;
            sf = shift;
            int stop = s_stop;
            __syncthreads();
            if (stop) break;
        }
    }
    if (tid == 0) s_scnt = 0;
    __syncthreads();
    for (int i = tid; i < cnt; i += BD) {
        unsigned long long key = keys[i];
        bool take = (sf >= 64) || ((key >> sf) >= prefix);
        if (take) {
            int p = atomicAdd(&s_scnt, 1);
            if (p < 512) sbuf[p] = key;
        }
    }
    __syncthreads();
    int sc = s_scnt < 512 ? s_scnt : 512;
    for (int i = tid; i < 512; i += BD)
        if (i >= sc) sbuf[i] = 0ULL;
    __syncthreads();
    // bitonic sort descending, 512 elements
    for (int kk2 = 2; kk2 <= 512; kk2 <<= 1) {
        for (int j = kk2 >> 1; j > 0; j >>= 1) {
            for (int i = tid; i < 512; i += BD) {
                int ixj = i ^ j;
                if (ixj > i) {
                    unsigned long long a = sbuf[i], b = sbuf[ixj];
                    bool desc = ((i & kk2) == 0);
                    if (desc ? (a < b) : (a > b)) { sbuf[i] = b; sbuf[ixj] = a; }
                }
            }
            __syncthreads();
        }
    }
    const int base = (t * CC + c) * KK;
    if (tid < KK && tid < r) {
        unsigned long long key = sbuf[tid];
        int v = (int)(0xFFFFFFFFu - (unsigned)(key & 0xFFFFFFFFull));
        outP[base + tid] = iford((unsigned)(key >> 32));
        outE[base + tid] = (float)v;
        g_last[c * KK + tid] = v;
        atomicOr(&g_delta[(unsigned)v], 1u << c);
    }
    // rare fill path: fewer than K valid candidates -> -1e9, lowest-index invalid nodes
    if (tid == 0 && r < KK) {
        int fill = r;
        for (int v = 0; v < NN && fill < KK; v++) {
            bool valid = (((g_nbr[v] >> c) & 1u) != 0u) && (g_known[v] == 0);
            if (!valid) {
                outP[base + fill] = -1e9f;
                outE[base + fill] = (float)v;
                g_last[c * KK + fill] = v;
                atomicOr(&g_delta[v], 1u << c);
                fill++;
            }
        }
    }
}

// ---------------- launch ----------------
extern "C" void kernel_launch(void* const* d_in, const int* in_sizes, int n_in,
                              void* d_out, int out_size) {
    const float* es    = (const float*)d_in[0];
    const int*   edges = (const int*)d_in[1];
    const int*   seeds = (const int*)d_in[2];
    const float* W     = (const float*)d_in[3];
    (void)n_in; (void)out_size;

    int e = in_sizes[1] / 2;
    const int* src = edges;
    const int* dst = edges + e;

    float* out  = (float*)d_out;
    float* outP = out;                       // [4,16,64] probs
    float* outE = out + NIT * CC * KK;       // [4,16,64] indices (as float)
    float* outH = out + 2 * NIT * CC * KK;   // [4,16,128] hx

    k_init0<<<256, 256>>>();
    k_init1<<<1, 256>>>(seeds);

    for (int t = 0; t < NIT; t++) {
        int kk = (t == 0) ? SS : KK;
        k_memory<<<CC, DD>>>(es, W, seeds, kk, t, outH);
        k_edges<<<2048, 256>>>(src, dst, e);
        k_promote<<<128, 256>>>();
        k_compact<<<512, 256>>>(es);
        k_topk<<<CC, 256>>>(outP, outE, t);
    }
}

// round 2
// speedup vs baseline: 1.0010x; 1.0010x over previous
#include <cuda_runtime.h>
#include <math.h>
#include <stdint.h>

#define NN 100000
#define DD 128
#define CC 16
#define SS 16
#define EE 3200000
#define KK 64
#define NIT 4

// ---------------- persistent device state (reset every launch) ----------------
__device__ unsigned int        g_nbr[NN];      // per-node 16-bit class neighbor mask (accumulative)
__device__ unsigned int        g_delta[NN];    // classes that newly added this node last selection
__device__ unsigned char      g_known[NN];
__device__ float               g_hx[CC * DD];
__device__ float               g_hxn[CC * DD]; // normalized hx
__device__ int                 g_last[CC * KK];
__device__ int                 g_candCnt[CC];
__device__ unsigned long long  g_candKeys[(size_t)CC * NN]; // 12.8 MB scratch

// ---------------- helpers ----------------
__device__ __forceinline__ unsigned ford(float f) {
    unsigned u = __float_as_uint(f);
    return (u >> 31) ? ~u : (u | 0x80000000u);
}
__device__ __forceinline__ float iford(unsigned u) {
    unsigned v = (u >> 31) ? (u & 0x7FFFFFFFu) : ~u;
    return __uint_as_float(v);
}

// ---------------- init ----------------
__global__ void k_init0() {
    int stride = gridDim.x * blockDim.x;
    for (int v = blockIdx.x * blockDim.x + threadIdx.x; v < NN; v += stride) {
        g_nbr[v] = 0u;
        g_delta[v] = 0u;
        g_known[v] = 0;
    }
}
__global__ void k_init1(const int* __restrict__ seeds) {
    int tid = threadIdx.x; // 256 = C*S
    if (tid < CC * SS) {
        int c = tid >> 4;
        int v = seeds[tid];
        g_known[v] = 1;
        atomicOr(&g_delta[v], 1u << c);
    }
}

// ---------------- memory step: hx = tanh((attend(es[last], q) [+hx]) @ W) ----------------
__global__ void k_memory(const float* __restrict__ es, const float* __restrict__ W,
                         const int* __restrict__ seeds, int kk, int t,
                         float* __restrict__ outHxes) {
    const int c = blockIdx.x;
    const int d = threadIdx.x; // 128 threads
    __shared__ float s_inp[KK * DD];
    __shared__ float s_q[DD];
    __shared__ float s_a[KK];
    __shared__ float s_pre[DD];
    __shared__ float s_red[4];

    const int* lp = (t == 0) ? (seeds + c * kk) : (g_last + c * KK);

    for (int j = 0; j < kk; j++) {
        int node = lp[j];
        s_inp[j * DD + d] = es[(size_t)node * DD + d];
    }
    float hprev = (t > 0) ? g_hx[c * DD + d] : 0.0f;
    if (t == 0) {
        float s = 0.0f;
        for (int j = 0; j < kk; j++) s += s_inp[j * DD + d];
        s_q[d] = s / (float)kk;
    } else {
        s_q[d] = hprev;
    }
    __syncthreads();

    // logits[j] = dot(inp_j, q) / sqrt(D)
    int lane = d & 31, wid = d >> 5;
    for (int j = wid; j < kk; j += 4) {
        float p = 0.0f;
#pragma unroll
        for (int q = 0; q < 4; q++) {
            int dd = lane + 32 * q;
            p += s_inp[j * DD + dd] * s_q[dd];
        }
#pragma unroll
        for (int o = 16; o; o >>= 1) p += __shfl_xor_sync(0xffffffffu, p, o);
        if (lane == 0) s_a[j] = p / sqrtf(128.0f);
    }
    __syncthreads();
    if (d == 0) {
        float m = s_a[0];
        for (int j = 1; j < kk; j++) m = fmaxf(m, s_a[j]);
        float sum = 0.0f;
        for (int j = 0; j < kk; j++) { float e = expf(s_a[j] - m); s_a[j] = e; sum += e; }
        for (int j = 0; j < kk; j++) s_a[j] /= sum;
    }
    __syncthreads();
    float ctx = 0.0f;
    for (int j = 0; j < kk; j++) ctx += s_a[j] * s_inp[j * DD + d];
    s_pre[d] = ctx + hprev;
    __syncthreads();

    float acc = 0.0f;
    for (int i = 0; i < DD; i++) acc += s_pre[i] * W[i * DD + d];
    float h = tanhf(acc);
    g_hx[c * DD + d] = h;
    outHxes[(t * CC + c) * DD + d] = h;

    float ss = h * h;
#pragma unroll
    for (int o = 16; o; o >>= 1) ss += __shfl_xor_sync(0xffffffffu, ss, o);
    if (lane == 0) s_red[wid] = ss;
    __syncthreads();
    float ns = s_red[0] + s_red[1] + s_red[2] + s_red[3];
    g_hxn[c * DD + d] = h / (sqrtf(ns) + 1e-8f);
    if (d == 0) g_candCnt[c] = 0;
}

// ---------------- incremental neighbor-mask update over edges ----------------
__global__ void k_edges(const int* __restrict__ src, const int* __restrict__ dst, int e) {
    int stride = gridDim.x * blockDim.x;
    int gt = blockIdx.x * blockDim.x + threadIdx.x;
    int e4 = e >> 2;
    const int4* s4 = reinterpret_cast<const int4*>(src);
    for (int i = gt; i < e4; i += stride) {
        int4 s = s4[i];
        unsigned m;
        m = g_delta[s.x]; if (m) atomicOr(&g_nbr[dst[4 * i + 0]], m);
        m = g_delta[s.y]; if (m) atomicOr(&g_nbr[dst[4 * i + 1]], m);
        m = g_delta[s.z]; if (m) atomicOr(&g_nbr[dst[4 * i + 2]], m);
        m = g_delta[s.w]; if (m) atomicOr(&g_nbr[dst[4 * i + 3]], m);
    }
    int tail = e & 3, base = e - tail;
    if (gt < tail) {
        int s = src[base + gt];
        unsigned m = g_delta[s];
        if (m) atomicOr(&g_nbr[dst[base + gt]], m);
    }
}

// ---------------- promote last selections to known, clear delta ----------------
__global__ void k_promote() {
    int stride = gridDim.x * blockDim.x;
    for (int v = blockIdx.x * blockDim.x + threadIdx.x; v < NN; v += stride) {
        unsigned m = g_delta[v];
        if (m) { g_known[v] = 1; g_delta[v] = 0u; }
    }
}

// ---------------- candidate compaction + cosine scoring (warp per node) ----------------
__global__ void k_compact(const float* __restrict__ es) {
    __shared__ float sh[CC * DD];
    for (int i = threadIdx.x; i < CC * DD; i += blockDim.x) sh[i] = g_hxn[i];
    __syncthreads();
    const int lane = threadIdx.x & 31;
    const int gw = (blockIdx.x * blockDim.x + threadIdx.x) >> 5;
    const int nw = (gridDim.x * blockDim.x) >> 5;
    for (int v = gw; v < NN; v += nw) {
        unsigned m = g_nbr[v];
        if (m == 0u) continue;
        if (g_known[v]) continue;
        const float4 r = reinterpret_cast<const float4*>(es)[(size_t)v * 32 + lane];
        float ss = r.x * r.x + r.y * r.y + r.z * r.z + r.w * r.w;
#pragma unroll
        for (int o = 16; o; o >>= 1) ss += __shfl_xor_sync(0xffffffffu, ss, o);
        float inv = 1.0f / (sqrtf(ss) + 1e-8f);
        while (m) {
            int c = __ffs(m) - 1;
            m &= m - 1;
            const float4 h = reinterpret_cast<const float4*>(sh + c * DD)[lane];
            float dp = r.x * h.x + r.y * h.y + r.z * h.z + r.w * h.w;
#pragma unroll
            for (int o = 16; o; o >>= 1) dp += __shfl_xor_sync(0xffffffffu, dp, o);
            if (lane == 0) {
                float score = dp * inv;
                unsigned long long key =
                    ((unsigned long long)ford(score) << 32) |
                    (unsigned long long)(0xFFFFFFFFu - (unsigned)v);
                int p = atomicAdd(&g_candCnt[c], 1);
                g_candKeys[(size_t)c * NN + p] = key;
            }
        }
    }
}

// ---------------- exact top-K per class: radix-select threshold + bitonic sort ----------------
__global__ void k_topk(float* __restrict__ outP, float* __restrict__ outE, int t) {
    const int c = blockIdx.x;
    const int tid = threadIdx.x;
    const int BD = 256;
    __shared__ unsigned int hist[4096];
    __shared__ unsigned long long sbuf[512];
    __shared__ int s_b, s_cum, s_stop, s_scnt;

    const unsigned long long* keys = g_candKeys + (size_t)c * NN;
    int cnt = g_candCnt[c];
    int r = cnt < KK ? cnt : KK;

    unsigned long long prefix = 0ULL;
    int sf = 64;
    if (cnt > 256) {
        int rr = r;
        for (int shift = 52; shift >= 4; shift -= 12) {
            for (int i = tid; i < 4096; i += BD) hist[i] = 0u;
            __syncthreads();
            for (int i = tid; i < cnt; i += BD) {
                unsigned long long key = keys[i];
                if (sf >= 64 || (key >> sf) == prefix)
                    atomicAdd(&hist[(unsigned)((key >> shift) & 0xFFFULL)], 1u);
            }
            __syncthreads();
            if (tid == 0) {
                int cum = 0, b = 4095;
                for (; b > 0; --b) {
                    int h = (int)hist[b];
                    if (cum + h >= rr) break;
                    cum += h;
                }
                s_b = b;
                s_cum = cum;
                int aboveTot = (r - rr) + cum;
                s_stop = (aboveTot + (int)hist[b] <= 256) ? 1 : 0;
            }
            __syncthreads();
            prefix = (prefix << 12) | (unsigned long long)s_b;
            rr -= s_cum;
            sf = shift;
            int stop = s_stop;
            __syncthreads();
            if (stop) break;
        }
    }
    if (tid == 0) s_scnt = 0;
    __syncthreads();
    for (int i = tid; i < cnt; i += BD) {
        unsigned long long key = keys[i];
        bool take = (sf >= 64) || ((key >> sf) >= prefix);
        if (take) {
            int p = atomicAdd(&s_scnt, 1);
            if (p < 512) sbuf[p] = key;
        }
    }
    __syncthreads();
    int sc = s_scnt < 512 ? s_scnt : 512;
    for (int i = tid; i < 512; i += BD)
        if (i >= sc) sbuf[i] = 0ULL;
    __syncthreads();
    // bitonic sort descending, 512 elements
    for (int kk2 = 2; kk2 <= 512; kk2 <<= 1) {
        for (int j = kk2 >> 1; j > 0; j >>= 1) {
            for (int i = tid; i < 512; i += BD) {
                int ixj = i ^ j;
                if (ixj > i) {
                    unsigned long long a = sbuf[i], b = sbuf[ixj];
                    bool desc = ((i & kk2) == 0);
                    if (desc ? (a < b) : (a > b)) { sbuf[i] = b; sbuf[ixj] = a; }
                }
            }
            __syncthreads();
        }
    }
    const int base = (t * CC + c) * KK;
    if (tid < KK && tid < r) {
        unsigned long long key = sbuf[tid];
        int v = (int)(0xFFFFFFFFu - (unsigned)(key & 0xFFFFFFFFull));
        outP[base + tid] = iford((unsigned)(key >> 32));
        outE[base + tid] = (float)v;
        g_last[c * KK + tid] = v;
        atomicOr(&g_delta[(unsigned)v], 1u << c);
    }
    // rare fill path: fewer than K valid candidates -> -1e9, lowest-index invalid nodes
    if (tid == 0 && r < KK) {
        int fill = r;
        for (int v = 0; v < NN && fill < KK; v++) {
            bool valid = (((g_nbr[v] >> c) & 1u) != 0u) && (g_known[v] == 0);
            if (!valid) {
                outP[base + fill] = -1e9f;
                outE[base + fill] = (float)v;
                g_last[c * KK + fill] = v;
                atomicOr(&g_delta[v], 1u << c);
                fill++;
            }
        }
    }
}

// ---------------- launch ----------------
extern "C" void kernel_launch(void* const* d_in, const int* in_sizes, int n_in,
                              void* d_out, int out_size) {
    const float* es    = (const float*)d_in[0];
    const int*   edges = (const int*)d_in[1];
    const int*   seeds = (const int*)d_in[2];
    const float* W     = (const float*)d_in[3];
    (void)n_in; (void)out_size;

    int e = in_sizes[1] / 2;
    const int* src = edges;
    const int* dst = edges + e;

    float* out  = (float*)d_out;
    float* outP = out;                       // [4,16,64] probs
    float* outE = out + NIT * CC * KK;       // [4,16,64] indices (as float)
    float* outH = out + 2 * NIT * CC * KK;   // [4,16,128] hx

    k_init0<<<256, 256>>>();
    k_init1<<<1, 256>>>(seeds);

    for (int t = 0; t < NIT; t++) {
        int kk = (t == 0) ? SS : KK;
        k_memory<<<CC, DD>>>(es, W, seeds, kk, t, outH);
        k_edges<<<2048, 256>>>(src, dst, e);
        k_promote<<<128, 256>>>();
        k_compact<<<512, 256>>>(es);
        k_topk<<<CC, 256>>>(outP, outE, t);
    }
}

// round 3
// speedup vs baseline: 1.0124x; 1.0114x over previous
#include <cuda_runtime.h>
#include <math.h>
#include <stdint.h>

#define NN 100000
#define DD 128
#define CC 16
#define SS 16
#define EE 3200000
#define KK 64
#define NIT 4

// ---------------- persistent device state (reset every launch) ----------------
__device__ unsigned int        g_nbr[NN];      // per-node 16-bit class neighbor mask (accumulative)
__device__ unsigned int        g_delta[NN];    // classes that newly added this node last selection
__device__ unsigned char      g_known[NN];
__device__ float               g_hx[CC * DD];
__device__ float               g_hxn[CC * DD]; // normalized hx
__device__ int                 g_last[CC * KK];
__device__ int                 g_candCnt[CC];
__device__ unsigned long long  g_candKeys[(size_t)CC * NN]; // 12.8 MB scratch

// ---------------- helpers ----------------
__device__ __forceinline__ unsigned ford(float f) {
    unsigned u = __float_as_uint(f);
    return (u >> 31) ? ~u : (u | 0x80000000u);
}
__device__ __forceinline__ float iford(unsigned u) {
    unsigned v = (u >> 31) ? (u & 0x7FFFFFFFu) : ~u;
    return __uint_as_float(v);
}

// ---------------- init ----------------
__global__ void k_init0() {
    int stride = gridDim.x * blockDim.x;
    for (int v = blockIdx.x * blockDim.x + threadIdx.x; v < NN; v += stride) {
        g_nbr[v] = 0u;
        g_delta[v] = 0u;
        g_known[v] = 0;
    }
}
__global__ void k_init1(const int* __restrict__ seeds) {
    int tid = threadIdx.x; // 256 = C*S
    if (tid < CC * SS) {
        int c = tid >> 4;
        int v = seeds[tid];
        g_known[v] = 1;
        atomicOr(&g_delta[v], 1u << c);
    }
}

// ---------------- memory step: hx = tanh((attend(es[last], q) [+hx]) @ W) ----------------
__global__ void k_memory(const float* __restrict__ es, const float* __restrict__ W,
                         const int* __restrict__ seeds, int kk, int t,
                         float* __restrict__ outHxes) {
    const int c = blockIdx.x;
    const int d = threadIdx.x; // 128 threads
    __shared__ float s_inp[KK * DD];
    __shared__ float s_q[DD];
    __shared__ float s_a[KK];
    __shared__ float s_pre[DD];
    __shared__ float s_red[4];

    const int* lp = (t == 0) ? (seeds + c * kk) : (g_last + c * KK);

    for (int j = 0; j < kk; j++) {
        int node = lp[j];
        s_inp[j * DD + d] = es[(size_t)node * DD + d];
    }
    float hprev = (t > 0) ? g_hx[c * DD + d] : 0.0f;
    if (t == 0) {
        float s = 0.0f;
        for (int j = 0; j < kk; j++) s += s_inp[j * DD + d];
        s_q[d] = s / (float)kk;
    } else {
        s_q[d] = hprev;
    }
    __syncthreads();

    // logits[j] = dot(inp_j, q) / sqrt(D)
    int lane = d & 31, wid = d >> 5;
    for (int j = wid; j < kk; j += 4) {
        float p = 0.0f;
#pragma unroll
        for (int q = 0; q < 4; q++) {
            int dd = lane + 32 * q;
            p += s_inp[j * DD + dd] * s_q[dd];
        }
#pragma unroll
        for (int o = 16; o; o >>= 1) p += __shfl_xor_sync(0xffffffffu, p, o);
        if (lane == 0) s_a[j] = p / sqrtf(128.0f);
    }
    __syncthreads();
    if (d == 0) {
        float m = s_a[0];
        for (int j = 1; j < kk; j++) m = fmaxf(m, s_a[j]);
        float sum = 0.0f;
        for (int j = 0; j < kk; j++) { float e = expf(s_a[j] - m); s_a[j] = e; sum += e; }
        for (int j = 0; j < kk; j++) s_a[j] /= sum;
    }
    __syncthreads();
    float ctx = 0.0f;
    for (int j = 0; j < kk; j++) ctx += s_a[j] * s_inp[j * DD + d];
    s_pre[d] = ctx + hprev;
    __syncthreads();

    float acc = 0.0f;
    for (int i = 0; i < DD; i++) acc += s_pre[i] * W[i * DD + d];
    float h = tanhf(acc);
    g_hx[c * DD + d] = h;
    outHxes[(t * CC + c) * DD + d] = h;

    float ss = h * h;
#pragma unroll
    for (int o = 16; o; o >>= 1) ss += __shfl_xor_sync(0xffffffffu, ss, o);
    if (lane == 0) s_red[wid] = ss;
    __syncthreads();
    float ns = s_red[0] + s_red[1] + s_red[2] + s_red[3];
    g_hxn[c * DD + d] = h / (sqrtf(ns) + 1e-8f);
    if (d == 0) g_candCnt[c] = 0;
}

// ---------------- incremental neighbor-mask update over edges ----------------
__global__ void k_edges(const int* __restrict__ src, const int* __restrict__ dst, int e) {
    int stride = gridDim.x * blockDim.x;
    int gt = blockIdx.x * blockDim.x + threadIdx.x;
    int e4 = e >> 2;
    const int4* s4 = reinterpret_cast<const int4*>(src);
    for (int i = gt; i < e4; i += stride) {
        int4 s = s4[i];
        unsigned m;
        m = g_delta[s.x]; if (m) atomicOr(&g_nbr[dst[4 * i + 0]], m);
        m = g_delta[s.y]; if (m) atomicOr(&g_nbr[dst[4 * i + 1]], m);
        m = g_delta[s.z]; if (m) atomicOr(&g_nbr[dst[4 * i + 2]], m);
        m = g_delta[s.w]; if (m) atomicOr(&g_nbr[dst[4 * i + 3]], m);
    }
    int tail = e & 3, base = e - tail;
    if (gt < tail) {
        int s = src[base + gt];
        unsigned m = g_delta[s];
        if (m) atomicOr(&g_nbr[dst[base + gt]], m);
    }
}

// ---------------- promote last selections to known, clear delta ----------------
__global__ void k_promote() {
    int stride = gridDim.x * blockDim.x;
    for (int v = blockIdx.x * blockDim.x + threadIdx.x; v < NN; v += stride) {
        unsigned m = g_delta[v];
        if (m) { g_known[v] = 1; g_delta[v] = 0u; }
    }
}

// ---------------- candidate compaction + cosine scoring (warp per node) ----------------
__global__ void k_compact(const float* __restrict__ es) {
    __shared__ float sh[CC * DD];
    for (int i = threadIdx.x; i < CC * DD; i += blockDim.x) sh[i] = g_hxn[i];
    __syncthreads();
    const int lane = threadIdx.x & 31;
    const int gw = (blockIdx.x * blockDim.x + threadIdx.x) >> 5;
    const int nw = (gridDim.x * blockDim.x) >> 5;
    for (int v = gw; v < NN; v += nw) {
        unsigned m = g_nbr[v];
        if (m == 0u) continue;
        if (g_known[v]) continue;
        const float4 r = reinterpret_cast<const float4*>(es)[(size_t)v * 32 + lane];
        float ss = r.x * r.x + r.y * r.y + r.z * r.z + r.w * r.w;
#pragma unroll
        for (int o = 16; o; o >>= 1) ss += __shfl_xor_sync(0xffffffffu, ss, o);
        float inv = 1.0f / (sqrtf(ss) + 1e-8f);
        while (m) {
            int c = __ffs(m) - 1;
            m &= m - 1;
            const float4 h = reinterpret_cast<const float4*>(sh + c * DD)[lane];
            float dp = r.x * h.x + r.y * h.y + r.z * h.z + r.w * h.w;
#pragma unroll
            for (int o = 16; o; o >>= 1) dp += __shfl_xor_sync(0xffffffffu, dp, o);
            if (lane == 0) {
                float score = dp * inv;
                unsigned long long key =
                    ((unsigned long long)ford(score) << 32) |
                    (unsigned long long)(0xFFFFFFFFu - (unsigned)v);
                int p = atomicAdd(&g_candCnt[c], 1);
                g_candKeys[(size_t)c * NN + p] = key;
            }
        }
    }
}

// ---------------- exact top-K per class: radix-select threshold + bitonic sort ----------------
__global__ void k_topk(float* __restrict__ outP, float* __restrict__ outE, int t) {
    const int c = blockIdx.x;
    const int tid = threadIdx.x;
    const int BD = 256;
    __shared__ unsigned int hist[4096];
    __shared__ unsigned long long sbuf[512];
    __shared__ int s_b, s_cum, s_stop, s_scnt;

    const unsigned long long* keys = g_candKeys + (size_t)c * NN;
    int cnt = g_candCnt[c];
    int r = cnt < KK ? cnt : KK;

    unsigned long long prefix = 0ULL;
    int sf = 64;
    if (cnt > 256) {
        int rr = r;
        for (int shift = 52; shift >= 4; shift -= 12) {
            for (int i = tid; i < 4096; i += BD) hist[i] = 0u;
            __syncthreads();
            for (int i = tid; i < cnt; i += BD) {
                unsigned long long key = keys[i];
                if (sf >= 64 || (key >> sf) == prefix)
                    atomicAdd(&hist[(unsigned)((key >> shift) & 0xFFFULL)], 1u);
            }
            __syncthreads();
            if (tid == 0) {
                int cum = 0, b = 4095;
                for (; b > 0; --b) {
                    int h = (int)hist[b];
                    if (cum + h >= rr) break;
                    cum += h;
                }
                s_b = b;
                s_cum = cum;
                int aboveTot = (r - rr) + cum;
                s_stop = (aboveTot + (int)hist[b] <= 256) ? 1 : 0;
            }
            __syncthreads();
            prefix = (prefix << 12) | (unsigned long long)s_b;
            rr -= s_cum;
            sf = shift;
            int stop = s_stop;
            __syncthreads();
            if (stop) break;
        }
    }
    if (tid == 0) s_scnt = 0;
    __syncthreads();
    for (int i = tid; i < cnt; i += BD) {
        unsigned long long key = keys[i];
        bool take = (sf >= 64) || ((key >> sf) >= prefix);
        if (take) {
            int p = atomicAdd(&s_scnt, 1);
            if (p < 512) sbuf[p] = key;
        }
    }
    __syncthreads();
    int sc = s_scnt < 512 ? s_scnt : 512;
    for (int i = tid; i < 512; i += BD)
        if (i >= sc) sbuf[i] = 0ULL;
    __syncthreads();
    // bitonic sort descending, 512 elements
    for (int kk2 = 2; kk2 <= 512; kk2 <<= 1) {
        for (int j = kk2 >> 1; j > 0; j >>= 1) {
            for (int i = tid; i < 512; i += BD) {
                int ixj = i ^ j;
                if (ixj > i) {
                    unsigned long long a = sbuf[i], b = sbuf[ixj];
                    bool desc = ((i & kk2) == 0);
                    if (desc ? (a < b) : (a > b)) { sbuf[i] = b; sbuf[ixj] = a; }
                }
            }
            __syncthreads();
        }
    }
    const int base = (t * CC + c) * KK;
    if (tid < KK && tid < r) {
        unsigned long long key = sbuf[tid];
        int v = (int)(0xFFFFFFFFu - (unsigned)(key & 0xFFFFFFFFull));
        outP[base + tid] = iford((unsigned)(key >> 32));
        outE[base + tid] = (float)v;
        g_last[c * KK + tid] = v;
        atomicOr(&g_delta[(unsigned)v], 1u << c);
    }
    // rare fill path: fewer than K valid candidates -> -1e9, lowest-index invalid nodes
    if (tid == 0 && r < KK) {
        int fill = r;
        for (int v = 0; v < NN && fill < KK; v++) {
            bool valid = (((g_nbr[v] >> c) & 1u) != 0u) && (g_known[v] == 0);
            if (!valid) {
                outP[base + fill] = -1e9f;
                outE[base + fill] = (float)v;
                g_last[c * KK + fill] = v;
                atomicOr(&g_delta[v], 1u << c);
                fill++;
            }
        }
    }
}

// ---------------- launch ----------------
extern "C" void kernel_launch(void* const* d_in, const int* in_sizes, int n_in,
                              void* d_out, int out_size) {
    const float* es    = (const float*)d_in[0];
    const int*   edges = (const int*)d_in[1];
    const int*   seeds = (const int*)d_in[2];
    const float* W     = (const float*)d_in[3];
    (void)n_in; (void)out_size;

    int e = in_sizes[1] / 2;
    const int* src = edges;
    const int* dst = edges + e;

    float* out  = (float*)d_out;
    float* outP = out;                       // [4,16,64] probs
    float* outE = out + NIT * CC * KK;       // [4,16,64] indices (as float)
    float* outH = out + 2 * NIT * CC * KK;   // [4,16,128] hx

    k_init0<<<256, 256>>>();
    k_init1<<<1, 256>>>(seeds);

    for (int t = 0; t < NIT; t++) {
        int kk = (t == 0) ? SS : KK;
        k_memory<<<CC, DD>>>(es, W, seeds, kk, t, outH);
        k_edges<<<2048, 256>>>(src, dst, e);
        k_promote<<<128, 256>>>();
        k_compact<<<512, 256>>>(es);
        k_topk<<<CC, 256>>>(outP, outE, t);
    }
}